// round 1
// baseline (speedup 1.0000x reference)
#include <cuda_runtime.h>
#include <cuda_bf16.h>

// BallQuery: for each of N1 query points, the first K points2 (in index order)
// with squared distance <= R2. Outputs concatenated as float32:
//   [0,            N1*K)        mapping (indices, 0-padded)
//   [N1*K,         N1*K+N1)     counts  (min(#within, K))
//   [N1*K+N1,      +N1*K*3)     gathered neighbor xyz (0-padded)

#define N1q 8192
#define N2q 8192
#define KNB 32
#define WPB 16                    // warps (queries) per block
#define NTHREADS (WPB * 32)       // 512
#define NBLOCKS (N1q / WPB)       // 512
#define SMEM_BYTES (N2q * 16)     // 8192 * float4 = 128 KB

__global__ void __launch_bounds__(NTHREADS, 1)
ball_query_kernel(const float* __restrict__ p1,
                  const float* __restrict__ p2,
                  float* __restrict__ out)
{
    extern __shared__ float4 sp[];   // points2 as (x, y, z, |p|^2)

    const int tid = threadIdx.x;

    // Stage points2 into shared memory, precomputing |p2|^2 with the exact
    // op order the reference uses: (x*x + y*y) + z*z, no FMA contraction.
    for (int j = tid; j < N2q; j += NTHREADS) {
        float x = p2[3 * j + 0];
        float y = p2[3 * j + 1];
        float z = p2[3 * j + 2];
        float b = __fadd_rn(__fadd_rn(__fmul_rn(x, x), __fmul_rn(y, y)),
                            __fmul_rn(z, z));
        sp[j] = make_float4(x, y, z, b);
    }
    __syncthreads();

    const int warp = tid >> 5;
    const int lane = tid & 31;
    const int q = blockIdx.x * WPB + warp;

    // Query point (broadcast load) and its squared norm, same op order.
    const float qx = p1[3 * q + 0];
    const float qy = p1[3 * q + 1];
    const float qz = p1[3 * q + 2];
    const float a = __fadd_rn(__fadd_rn(__fmul_rn(qx, qx), __fmul_rn(qy, qy)),
                              __fmul_rn(qz, qz));

    // Threshold: python double 0.1*0.1 demoted to f32 (what jnp compares with).
    const float R2 = (float)(0.1 * 0.1);

    float* __restrict__ mapf = out;                       // [N1*K]
    float* __restrict__ cntf = out + N1q * KNB;           // [N1]
    float* __restrict__ outf = out + N1q * KNB + N1q;     // [N1*K*3]

    int cnt = 0;  // warp-uniform (updated from ballot)

    #pragma unroll 4
    for (int it = 0; it < N2q / 32; ++it) {
        if (cnt >= KNB) break;   // warp-uniform early exit
        const int j = it * 32 + lane;
        const float4 p = sp[j];

        // Gram-trick distance, replicating reference rounding:
        //   c  = (qx*x + qy*y) + qz*z
        //   d2 = (a + b) - 2*c
        const float c = __fadd_rn(
            __fadd_rn(__fmul_rn(qx, p.x), __fmul_rn(qy, p.y)),
            __fmul_rn(qz, p.z));
        const float d2 = __fsub_rn(__fadd_rn(a, p.w), __fmul_rn(2.0f, c));

        const bool hit = (d2 <= R2);
        const unsigned mask = __ballot_sync(0xffffffffu, hit);
        if (mask) {
            const int slot = cnt + __popc(mask & ((1u << lane) - 1u));
            if (hit && slot < KNB) {
                mapf[q * KNB + slot] = (float)j;
                float* o = outf + (size_t)(q * KNB + slot) * 3;
                o[0] = p.x;
                o[1] = p.y;
                o[2] = p.z;
            }
            cnt += __popc(mask);
        }
    }

    const int cc = (cnt < KNB) ? cnt : KNB;

    // Zero-pad unused slots (d_out is poisoned, must write everything).
    if (lane >= cc) {
        mapf[q * KNB + lane] = 0.0f;
        float* o = outf + (size_t)(q * KNB + lane) * 3;
        o[0] = 0.0f;
        o[1] = 0.0f;
        o[2] = 0.0f;
    }
    if (lane == 0) cntf[q] = (float)cc;
}

extern "C" void kernel_launch(void* const* d_in, const int* in_sizes, int n_in,
                              void* d_out, int out_size)
{
    (void)in_sizes; (void)n_in; (void)out_size;
    const float* p1 = (const float*)d_in[0];
    const float* p2 = (const float*)d_in[1];
    float* out = (float*)d_out;

    cudaFuncSetAttribute(ball_query_kernel,
                         cudaFuncAttributeMaxDynamicSharedMemorySize,
                         SMEM_BYTES);
    ball_query_kernel<<<NBLOCKS, NTHREADS, SMEM_BYTES>>>(p1, p2, out);
}

// round 2
// speedup vs baseline: 1.8442x; 1.8442x over previous
#include <cuda_runtime.h>
#include <cuda_bf16.h>

// BallQuery: for each of N1 query points, the first K points2 (in index order)
// with squared distance <= R2. Outputs concatenated as float32:
//   [0,            N1*K)        mapping (indices, 0-padded)
//   [N1*K,         N1*K+N1)     counts  (min(#within, K))
//   [N1*K+N1,      +N1*K*3)     gathered neighbor xyz (0-padded)

#define N1q 8192
#define N2q 8192
#define KNB 32
#define WPB 32                    // warps (queries) per block
#define NTHREADS (WPB * 32)       // 1024
#define NBLOCKS (N1q / WPB)       // 256
#define SMEM_BYTES (N2q * 16)     // 8192 * float4 = 128 KB

__global__ void __launch_bounds__(NTHREADS, 1)
ball_query_kernel(const float* __restrict__ p1,
                  const float* __restrict__ p2,
                  float* __restrict__ out)
{
    extern __shared__ float4 sp[];   // points2 as (x, y, z, |p|^2)

    const int tid = threadIdx.x;

    // Stage points2 into shared memory, precomputing |p2|^2 with the exact
    // op order the reference uses: (x*x + y*y) + z*z, no FMA contraction.
    for (int j = tid; j < N2q; j += NTHREADS) {
        float x = p2[3 * j + 0];
        float y = p2[3 * j + 1];
        float z = p2[3 * j + 2];
        float b = __fadd_rn(__fadd_rn(__fmul_rn(x, x), __fmul_rn(y, y)),
                            __fmul_rn(z, z));
        sp[j] = make_float4(x, y, z, b);
    }
    __syncthreads();

    const int warp = tid >> 5;
    const int lane = tid & 31;
    const int q = blockIdx.x * WPB + warp;

    // Query point (broadcast load) and its squared norm, same op order.
    const float qx = p1[3 * q + 0];
    const float qy = p1[3 * q + 1];
    const float qz = p1[3 * q + 2];
    const float a = __fadd_rn(__fadd_rn(__fmul_rn(qx, qx), __fmul_rn(qy, qy)),
                              __fmul_rn(qz, qz));

    // Threshold: python double 0.1*0.1 demoted to f32 (what jnp compares with).
    const float R2 = (float)(0.1 * 0.1);

    float* __restrict__ mapq = out + (size_t)q * KNB;                   // mapping row
    float* __restrict__ cntf = out + (size_t)N1q * KNB;                 // counts
    float* __restrict__ outq = out + (size_t)N1q * KNB + N1q
                                   + (size_t)q * KNB * 3;               // xyz row

    int cnt = 0;  // warp-uniform (updated from ballots)
    const unsigned below = (1u << lane) - 1u;

    #pragma unroll 4
    for (int it = 0; it < N2q / 64; ++it) {
        if (cnt >= KNB) break;   // warp-uniform early exit

        const int j0 = it * 64 + lane;
        const int j1 = j0 + 32;
        const float4 pa = sp[j0];
        const float4 pb = sp[j1];

        // Gram-trick distance, replicating reference rounding:
        //   c  = (qx*x + qy*y) + qz*z ;  d2 = (a + b) - 2*c
        const float ca = __fadd_rn(
            __fadd_rn(__fmul_rn(qx, pa.x), __fmul_rn(qy, pa.y)),
            __fmul_rn(qz, pa.z));
        const float d2a = __fsub_rn(__fadd_rn(a, pa.w), __fmul_rn(2.0f, ca));

        const float cb = __fadd_rn(
            __fadd_rn(__fmul_rn(qx, pb.x), __fmul_rn(qy, pb.y)),
            __fmul_rn(qz, pb.z));
        const float d2b = __fsub_rn(__fadd_rn(a, pb.w), __fmul_rn(2.0f, cb));

        const bool hitA = (d2a <= R2);
        const bool hitB = (d2b <= R2);
        const unsigned maskA = __ballot_sync(0xffffffffu, hitA);
        const unsigned maskB = __ballot_sync(0xffffffffu, hitB);

        if (maskA | maskB) {
            const int popA = __popc(maskA);
            if (hitA) {
                const int slot = cnt + __popc(maskA & below);
                if (slot < KNB) {
                    mapq[slot] = (float)j0;
                    float* o = outq + slot * 3;
                    o[0] = pa.x; o[1] = pa.y; o[2] = pa.z;
                }
            }
            if (hitB) {
                const int slot = cnt + popA + __popc(maskB & below);
                if (slot < KNB) {
                    mapq[slot] = (float)j1;
                    float* o = outq + slot * 3;
                    o[0] = pb.x; o[1] = pb.y; o[2] = pb.z;
                }
            }
            cnt += popA + __popc(maskB);
        }
    }

    const int cc = (cnt < KNB) ? cnt : KNB;

    // Zero-pad unused slots (d_out is poisoned, must write everything).
    if (lane >= cc) {
        mapq[lane] = 0.0f;
        float* o = outq + lane * 3;
        o[0] = 0.0f; o[1] = 0.0f; o[2] = 0.0f;
    }
    if (lane == 0) cntf[q] = (float)cc;
}

extern "C" void kernel_launch(void* const* d_in, const int* in_sizes, int n_in,
                              void* d_out, int out_size)
{
    (void)in_sizes; (void)n_in; (void)out_size;
    const float* p1 = (const float*)d_in[0];
    const float* p2 = (const float*)d_in[1];
    float* out = (float*)d_out;

    cudaFuncSetAttribute(ball_query_kernel,
                         cudaFuncAttributeMaxDynamicSharedMemorySize,
                         SMEM_BYTES);
    ball_query_kernel<<<NBLOCKS, NTHREADS, SMEM_BYTES>>>(p1, p2, out);
}

// round 3
// speedup vs baseline: 3.6250x; 1.9657x over previous
#include <cuda_runtime.h>
#include <cuda_bf16.h>
#include <climits>

// BallQuery via uniform spatial grid.
// Outputs concatenated as float32:
//   [0,         N1*K)      mapping (indices, 0-padded)
//   [N1*K,      N1*K+N1)   counts  (min(#within, K))
//   [N1*K+N1,   +N1*K*3)   gathered neighbor xyz (0-padded)

#define NQ 8192
#define NP 8192
#define KNB 32
#define GRIDC 10
#define NCELL (GRIDC * GRIDC * GRIDC)
#define SCALEF 9.99f          // cell width 1/9.99 > radius -> +-1 cell coverage
#define CAP 128               // per-query hit buffer capacity
#define QWPB 16               // query warps per block

// Device scratch (no allocations allowed).
__device__ float4 g_sorted[NP];     // cell-sorted points: (x, y, z, |p|^2)
__device__ int    g_sidx[NP];       // original index of sorted point
__device__ int    g_cellId[NP];
__device__ int    g_count[NCELL];
__device__ int    g_start[NCELL + 1];
__device__ int    g_offset[NCELL];

__device__ __forceinline__ int cell_of(float x) {
    int c = __float2int_rd(__fmul_rn(x, SCALEF));
    return min(max(c, 0), GRIDC - 1);
}

__global__ void zero_kernel() {
    int i = threadIdx.x;
    if (i < NCELL) g_count[i] = 0;
}

__global__ void histo_kernel(const float* __restrict__ p2) {
    int i = blockIdx.x * blockDim.x + threadIdx.x;
    if (i >= NP) return;
    float x = p2[3 * i], y = p2[3 * i + 1], z = p2[3 * i + 2];
    int c = cell_of(x) + GRIDC * cell_of(y) + GRIDC * GRIDC * cell_of(z);
    g_cellId[i] = c;
    atomicAdd(&g_count[c], 1);
}

__global__ void scan_kernel() {
    __shared__ int s[1024];
    int t = threadIdx.x;
    int v = (t < NCELL) ? g_count[t] : 0;
    s[t] = v;
    __syncthreads();
    #pragma unroll
    for (int d = 1; d < 1024; d <<= 1) {
        int add = (t >= d) ? s[t - d] : 0;
        __syncthreads();
        s[t] += add;
        __syncthreads();
    }
    if (t < NCELL) {
        g_start[t + 1] = s[t];
        g_offset[t] = s[t] - v;   // exclusive prefix = scatter cursor
    }
    if (t == 0) g_start[0] = 0;
}

__global__ void scatter_kernel(const float* __restrict__ p2) {
    int i = blockIdx.x * blockDim.x + threadIdx.x;
    if (i >= NP) return;
    int c = g_cellId[i];
    int pos = atomicAdd(&g_offset[c], 1);
    float x = p2[3 * i], y = p2[3 * i + 1], z = p2[3 * i + 2];
    // |p|^2 with reference rounding: (x*x + y*y) + z*z, no FMA contraction.
    float b = __fadd_rn(__fadd_rn(__fmul_rn(x, x), __fmul_rn(y, y)),
                        __fmul_rn(z, z));
    g_sorted[pos] = make_float4(x, y, z, b);
    g_sidx[pos] = i;
}

// Warp bitonic ascending sort of 32*R ints, layout pos = lane + 32*r.
template <int R>
__device__ __forceinline__ void bitonic(int v[R], int lane) {
    const int n = 32 * R;
    #pragma unroll
    for (int k = 2; k <= n; k <<= 1) {
        #pragma unroll
        for (int j = k >> 1; j > 0; j >>= 1) {
            if (j >= 32) {
                const int jr = j >> 5;
                #pragma unroll
                for (int r = 0; r < R; ++r) {
                    const int pr = r ^ jr;
                    if (pr > r) {
                        const bool up = (((lane + 32 * r) & k) == 0);
                        int a = v[r], b = v[pr];
                        if ((a > b) == up) { v[r] = b; v[pr] = a; }
                    }
                }
            } else {
                #pragma unroll
                for (int r = 0; r < R; ++r) {
                    int part = __shfl_xor_sync(0xffffffffu, v[r], j);
                    const bool up = (((lane + 32 * r) & k) == 0);
                    const bool lowr = ((lane & j) == 0);
                    v[r] = (lowr == up) ? min(v[r], part) : max(v[r], part);
                }
            }
        }
    }
}

__global__ void __launch_bounds__(QWPB * 32)
query_kernel(const float* __restrict__ p1, float* __restrict__ out)
{
    __shared__ float4 hitbuf[QWPB][CAP];

    const int warp = threadIdx.x >> 5;
    const int lane = threadIdx.x & 31;
    const int q = blockIdx.x * QWPB + warp;

    const float qx = p1[3 * q], qy = p1[3 * q + 1], qz = p1[3 * q + 2];
    const float a = __fadd_rn(__fadd_rn(__fmul_rn(qx, qx), __fmul_rn(qy, qy)),
                              __fmul_rn(qz, qz));
    const float R2 = (float)(0.1 * 0.1);

    const int cx = cell_of(qx), cy = cell_of(qy), cz = cell_of(qz);
    const int xlo = max(cx - 1, 0), xhi = min(cx + 1, GRIDC - 1);
    const int ylo = max(cy - 1, 0), yhi = min(cy + 1, GRIDC - 1);
    const int zlo = max(cz - 1, 0), zhi = min(cz + 1, GRIDC - 1);

    const unsigned below = (1u << lane) - 1u;
    int cnt = 0;

    for (int ez = zlo; ez <= zhi; ++ez) {
        for (int ey = ylo; ey <= yhi; ++ey) {
            const int base = GRIDC * ey + GRIDC * GRIDC * ez;
            const int s = g_start[xlo + base];
            const int e = g_start[xhi + base + 1];  // x-contiguous row of 3 cells
            for (int t0 = s; t0 < e; t0 += 32) {
                const int t = t0 + lane;
                const bool act = (t < e);
                float4 p = make_float4(0.f, 0.f, 0.f, 4e30f);
                if (act) p = __ldg(&g_sorted[t]);
                // Gram-trick distance, reference rounding.
                const float c = __fadd_rn(
                    __fadd_rn(__fmul_rn(qx, p.x), __fmul_rn(qy, p.y)),
                    __fmul_rn(qz, p.z));
                const float d2 = __fsub_rn(__fadd_rn(a, p.w),
                                           __fmul_rn(2.0f, c));
                const bool hit = act && (d2 <= R2);
                const unsigned m = __ballot_sync(0xffffffffu, hit);
                if (m) {
                    if (hit) {
                        const int slot = cnt + __popc(m & below);
                        if (slot < CAP) {
                            const int idx = __ldg(&g_sidx[t]);
                            hitbuf[warp][slot] =
                                make_float4(p.x, p.y, p.z, __int_as_float(idx));
                        }
                    }
                    cnt += __popc(m);
                }
            }
        }
    }

    const int cc = min(cnt, KNB);
    const int nb = min(cnt, CAP);

    // Sort hit keys (idx<<7 | slot) ascending; idx unique -> deterministic.
    int key0;
    if (cnt <= 64) {
        int v[2];
        #pragma unroll
        for (int r = 0; r < 2; ++r) {
            const int slot = lane + 32 * r;
            v[r] = (slot < nb)
                ? ((__float_as_int(hitbuf[warp][slot].w) << 7) | slot)
                : INT_MAX;
        }
        bitonic<2>(v, lane);
        key0 = v[0];
    } else {
        int v[4];
        #pragma unroll
        for (int r = 0; r < 4; ++r) {
            const int slot = lane + 32 * r;
            v[r] = (slot < nb)
                ? ((__float_as_int(hitbuf[warp][slot].w) << 7) | slot)
                : INT_MAX;
        }
        bitonic<4>(v, lane);
        key0 = v[0];
    }

    float* __restrict__ mapq = out + (size_t)q * KNB;
    float* __restrict__ cntf = out + (size_t)NQ * KNB;
    float* __restrict__ outq = out + (size_t)NQ * KNB + NQ + (size_t)q * KNB * 3;

    if (lane < cc) {
        const int idx = key0 >> 7;
        const int slot = key0 & (CAP - 1);
        const float4 h = hitbuf[warp][slot];
        mapq[lane] = (float)idx;
        outq[3 * lane + 0] = h.x;
        outq[3 * lane + 1] = h.y;
        outq[3 * lane + 2] = h.z;
    } else {
        mapq[lane] = 0.0f;
        outq[3 * lane + 0] = 0.0f;
        outq[3 * lane + 1] = 0.0f;
        outq[3 * lane + 2] = 0.0f;
    }
    if (lane == 0) cntf[q] = (float)cc;
}

extern "C" void kernel_launch(void* const* d_in, const int* in_sizes, int n_in,
                              void* d_out, int out_size)
{
    (void)in_sizes; (void)n_in; (void)out_size;
    const float* p1 = (const float*)d_in[0];
    const float* p2 = (const float*)d_in[1];
    float* out = (float*)d_out;

    zero_kernel<<<1, 1024>>>();
    histo_kernel<<<NP / 256, 256>>>(p2);
    scan_kernel<<<1, 1024>>>();
    scatter_kernel<<<NP / 256, 256>>>(p2);
    query_kernel<<<NQ / QWPB, QWPB * 32>>>(p1, out);
}